// round 17
// baseline (speedup 1.0000x reference)
#include <cuda_runtime.h>
#include <cstdint>

#define B_SZ  32
#define T_LEN 2048
#define I_DIM 128
#define H_DIM 256

// Scratch (allocation-free rule: __device__ globals)
__device__ __align__(256) float g_xB[B_SZ * T_LEN * H_DIM];  // 67 MB
__device__ __align__(256) float g_hs[B_SZ * T_LEN * H_DIM];  // 67 MB
// L2 exchange buffer: [batch][parity][column] = {h bits, tag}. 128 KB.
__device__ __align__(256) uint2 g_xch[B_SZ][2][H_DIM];

// ---------------------------------------------------------------------------
// helpers
// ---------------------------------------------------------------------------
__device__ __forceinline__ uint32_t smem_u32(const void* p) {
    uint32_t a;
    asm("{ .reg .u64 t; cvta.to.shared.u64 t, %1; cvt.u32.u64 %0, t; }"
        : "=r"(a) : "l"(p));
    return a;
}

// packed fp32x2 FMA: full-rate FMA path on sm_103a (3-reg FFMA is half rate)
__device__ __forceinline__ void ffma2(unsigned long long& acc,
                                      unsigned long long a,
                                      unsigned long long b) {
    asm("fma.rn.f32x2 %0, %1, %2, %0;" : "+l"(acc) : "l"(a), "l"(b));
}
__device__ __forceinline__ unsigned long long pack2(float lo, float hi) {
    unsigned long long r;
    asm("mov.b64 %0, {%1, %2};" : "=l"(r) : "f"(lo), "f"(hi));
    return r;
}
__device__ __forceinline__ unsigned long long pack2u(uint32_t lo, uint32_t hi) {
    unsigned long long r;
    asm("mov.b64 %0, {%1, %2};" : "=l"(r) : "r"(lo), "r"(hi));
    return r;
}
__device__ __forceinline__ float2 unpack2(unsigned long long v) {
    float2 r;
    asm("mov.b64 {%0, %1}, %2;" : "=f"(r.x), "=f"(r.y) : "l"(v));
    return r;
}

// tanh(x) = 1 - 2/(exp(2x)+1), via MUFU.EX2 + MUFU.RCP. Abs err ~1e-7.
__device__ __forceinline__ float fast_tanh(float x) {
    float e, r;
    float t = x * 2.8853900817779268f;      // 2*log2(e)
    asm("ex2.approx.f32 %0, %1;" : "=f"(e) : "f"(t));
    float d = e + 1.0f;
    asm("rcp.approx.f32 %0, %1;" : "=f"(r) : "f"(d));
    return fmaf(-2.0f, r, 1.0f);
}

// ---------------------------------------------------------------------------
// tag reset — tags are monotone within one launch; graph replays reuse the
// buffer, so every launch must restart them at 0.
// ---------------------------------------------------------------------------
__global__ void zero_xch_kernel()
{
    int b = blockIdx.x;
    int t = threadIdx.x;                    // 0..255 == H_DIM
    g_xch[b][0][t] = make_uint2(0u, 0u);
    g_xch[b][1][t] = make_uint2(0u, 0u);
}

// ---------------------------------------------------------------------------
// Scan kernel: PAIR of plain CTAs per batch element (no clusters).
//   CTA pair (2b, 2b+1); rank = blockIdx.x & 1 owns output columns
//   j in [128*rank, 128*rank+128).
//   256 threads: jj = tid&127 (output col), q = tid>>7.
//   q0 warps consume the LOCALLY produced h half; q1 warps consume the
//   PEER half -> only q1 ever blocks.
//
//   R17 exchange — through L2 with relaxed-gpu SCALAR b64 atomics
//   (single-copy atomic by the PTX memory model -> the R16 DSMEM vector
//   tear is impossible by construction):
//     producer (q0): one st.relaxed.gpu.global.b64 of the tagged word
//       {h, tag=t+1} into g_xch[b][nxt][j], plus a local STS.64.
//     consumer (q1): each of the 128 threads polls its own word
//       g_xch[b][cur][kbase+jj] with ld.relaxed.gpu.global.b64 (~240cyc
//       L2 hit per poll) until tag >= t, mirrors it into local smem,
//       bar.sync 1,128, then all q1 threads dot out of local smem.
//   Clobber safety (double buffer by parity, same induction as R15):
//   my q0's overwrite of g_xch[nxt] (tag t+2) happens after my bar#1 of
//   step t+1, which my q1 reaches only after polling peer tag >= t+1,
//   which happens after the peer's q1 ALREADY read my tag-t words
//   (its poll precedes its STG by program order).
// ---------------------------------------------------------------------------
__global__ void __launch_bounds__(256, 1)
scan_kernel(const float* __restrict__ A)
{
    // tagged local state: [parity][global column] = {h bits, tag}
    __shared__ __align__(16) uint2 h_tag[2][H_DIM];
    __shared__ float scratch[128];                  // pair-reduce partials

    const int tid   = threadIdx.x;
    const int jj    = tid & 127;
    const int q     = tid >> 7;            // 0 or 1  (warp-uniform)
    const int rank  = blockIdx.x & 1;
    const int b     = blockIdx.x >> 1;
    const int j     = rank * 128 + jj;                 // global output column
    // q0 -> local half (rank*128), q1 -> peer half
    const int kbase = (int)(((q + rank) & 1) * 128);

    // --- A slice -> registers, packed as (A[k][j], A[k+1][j]) pairs --------
    unsigned long long Ar[64];
#pragma unroll
    for (int m = 0; m < 64; m++) {
        float a0 = A[(size_t)(kbase + 2 * m)     * H_DIM + j];
        float a1 = A[(size_t)(kbase + 2 * m + 1) * H_DIM + j];
        Ar[m] = pack2(a0, a1);
    }

    // --- init tagged local state: h=0, tag=0 --------------------------------
    h_tag[0][tid] = make_uint2(0u, 0u);    // tid covers 0..255 == H_DIM
    h_tag[1][tid] = make_uint2(0u, 0u);
    uint32_t htag_a = smem_u32(&h_tag[0][0]);
    __syncthreads();

    // --- xB prefetch pipeline (distance 2 hides DRAM latency) ---------------
    const float* xb_base = g_xB + ((size_t)b * T_LEN) * H_DIM + j;
    float*       hs_out  = g_hs + ((size_t)b * T_LEN) * H_DIM + j;
    float xb_pre[2] = {0.0f, 0.0f};
    if (q == 0) {
        xb_pre[0] = __ldg(xb_base);
        xb_pre[1] = __ldg(xb_base + H_DIM);
    }

    // L2 exchange addresses
    const uint2* poll_base = &g_xch[b][0][kbase + jj];  // q1 polls this (+parity)
    uint2*       pub_base  = &g_xch[b][0][j];           // q0 publishes this (+parity)

    // --- main scan loop -----------------------------------------------------
    for (int t = 0; t < T_LEN; t++) {
        const int cur = t & 1;
        const int nxt = cur ^ 1;

        // q1: poll own tagged word in L2 until the peer's step-t state
        // (tag >= t) appears; then mirror it into local smem.
        if (q == 1) {
            const uint2* gp = poll_base + cur * H_DIM;
            unsigned long long w;
            uint32_t tg;
            do {
                asm volatile("ld.relaxed.gpu.global.b64 %0, [%1];"
                             : "=l"(w) : "l"(gp) : "memory");
                tg = (uint32_t)(w >> 32);
            } while (tg < (uint32_t)t);
            uint32_t laddr = htag_a +
                             (uint32_t)((cur * H_DIM + kbase + jj) * 8);
            asm volatile("st.shared.b64 [%0], %1;"
                         :: "r"(laddr), "l"(w) : "memory");
            // all 128 q1 threads pulled their word -> whole half is local
            asm volatile("bar.sync 1, 128;" ::: "memory");
        }

        // dot over my 128 k values from the tagged array:
        // uint4 = {h_k, tag, h_k+1, tag} -> pack h_k,h_k+1 -> one ffma2.
        const uint4* hp =
            reinterpret_cast<const uint4*>(&h_tag[cur][kbase]);
        unsigned long long acc0 = 0ull, acc1 = 0ull, acc2 = 0ull, acc3 = 0ull;
#pragma unroll
        for (int m = 0; m < 64; m += 4) {
            uint4 w0 = hp[m + 0];
            uint4 w1 = hp[m + 1];
            uint4 w2 = hp[m + 2];
            uint4 w3 = hp[m + 3];
            ffma2(acc0, pack2u(w0.x, w0.z), Ar[m + 0]);
            ffma2(acc1, pack2u(w1.x, w1.z), Ar[m + 1]);
            ffma2(acc2, pack2u(w2.x, w2.z), Ar[m + 2]);
            ffma2(acc3, pack2u(w3.x, w3.z), Ar[m + 3]);
        }
        float2 u0 = unpack2(acc0), u1 = unpack2(acc1);
        float2 u2 = unpack2(acc2), u3 = unpack2(acc3);
        float partial = ((u0.x + u0.y) + (u1.x + u1.y)) +
                        ((u2.x + u2.y) + (u3.x + u3.y));

        if (q == 1) scratch[jj] = partial;
        __syncthreads();    // bar #1: scratch ready; q1 done with buf[cur]

        if (q == 0) {
            float tot = partial + scratch[jj] + xb_pre[t & 1];
            if (t + 2 < T_LEN)   // refill prefetch slot
                xb_pre[t & 1] = __ldg(xb_base + (size_t)(t + 2) * H_DIM);
            float hv = fast_tanh(tot);

            // tagged word {h bits, tag = t+1}
            unsigned long long payload =
                pack2u(__float_as_uint(hv), (uint32_t)(t + 1));

            if (t + 1 < T_LEN) {
                // publish to L2 FIRST (critical path: peer's poll)
                const uint2* gp = pub_base + nxt * H_DIM;
                asm volatile("st.relaxed.gpu.global.b64 [%0], %1;"
                             :: "l"(gp), "l"(payload) : "memory");
            }
            // local copy (my half), same tagged format
            uint32_t laddr = htag_a + (uint32_t)((nxt * H_DIM + j) * 8);
            asm volatile("st.shared.b64 [%0], %1;"
                         :: "r"(laddr), "l"(payload) : "memory");

            hs_out[(size_t)t * H_DIM] = hv;     // for out-GEMM
        }
        __syncthreads();    // bar #2: local half of buf[nxt] visible CTA-wide
    }
}

// ---------------------------------------------------------------------------
// fp32 tiled GEMM: C[M,N] = A[M,K] @ B[K,N], all row-major.
// 128x128 block tile, k-tile 16, 256 threads, 8x8 microtile, FFMA2 accums.
// (~90% of fp32 FMA roofline measured; unchanged.)
// ---------------------------------------------------------------------------
__global__ void __launch_bounds__(256)
gemm_f32(const float* __restrict__ Ag, const float* __restrict__ Bg,
         float* __restrict__ Cg, int M, int N, int K)
{
    __shared__ __align__(16) float As[16][128];   // transposed A tile
    __shared__ __align__(16) float Bs[16][128];

    const int tid = threadIdx.x;
    const int bm  = blockIdx.x * 128;
    const int bn  = blockIdx.y * 128;
    const int tx  = tid & 15;     // n direction
    const int ty  = tid >> 4;     // m direction
    const int m0  = ty * 8;
    const int n0  = tx * 8;

    unsigned long long acc[8][4];
#pragma unroll
    for (int i = 0; i < 8; i++)
#pragma unroll
        for (int p = 0; p < 4; p++) acc[i][p] = 0ull;

    for (int k0 = 0; k0 < K; k0 += 16) {
#pragma unroll
        for (int l = 0; l < 2; l++) {
            int v  = tid + l * 256;
            int r  = v >> 2;
            int c4 = v & 3;
            float4 a = *reinterpret_cast<const float4*>(
                &Ag[(size_t)(bm + r) * K + k0 + c4 * 4]);
            As[c4 * 4 + 0][r] = a.x;
            As[c4 * 4 + 1][r] = a.y;
            As[c4 * 4 + 2][r] = a.z;
            As[c4 * 4 + 3][r] = a.w;
        }
#pragma unroll
        for (int l = 0; l < 2; l++) {
            int v  = tid + l * 256;
            int kk = v >> 5;
            int c4 = v & 31;
            *reinterpret_cast<float4*>(&Bs[kk][c4 * 4]) =
                *reinterpret_cast<const float4*>(
                    &Bg[(size_t)(k0 + kk) * N + bn + c4 * 4]);
        }
        __syncthreads();

#pragma unroll
        for (int kk = 0; kk < 16; kk++) {
            float4 a0 = *reinterpret_cast<const float4*>(&As[kk][m0]);
            float4 a1 = *reinterpret_cast<const float4*>(&As[kk][m0 + 4]);
            ulonglong2 b0 = *reinterpret_cast<const ulonglong2*>(&Bs[kk][n0]);
            ulonglong2 b1 = *reinterpret_cast<const ulonglong2*>(&Bs[kk][n0 + 4]);

            unsigned long long ap[8];
            ap[0] = pack2(a0.x, a0.x); ap[1] = pack2(a0.y, a0.y);
            ap[2] = pack2(a0.z, a0.z); ap[3] = pack2(a0.w, a0.w);
            ap[4] = pack2(a1.x, a1.x); ap[5] = pack2(a1.y, a1.y);
            ap[6] = pack2(a1.z, a1.z); ap[7] = pack2(a1.w, a1.w);
            unsigned long long bv0 = b0.x, bv1 = b0.y, bv2 = b1.x, bv3 = b1.y;

#pragma unroll
            for (int i = 0; i < 8; i++) {
                ffma2(acc[i][0], ap[i], bv0);
                ffma2(acc[i][1], ap[i], bv1);
                ffma2(acc[i][2], ap[i], bv2);
                ffma2(acc[i][3], ap[i], bv3);
            }
        }
        __syncthreads();
    }

#pragma unroll
    for (int i = 0; i < 8; i++) {
        float o[8];
#pragma unroll
        for (int p = 0; p < 4; p++) {
            float2 u = unpack2(acc[i][p]);
            o[2 * p] = u.x; o[2 * p + 1] = u.y;
        }
        float4* dst = reinterpret_cast<float4*>(
            &Cg[(size_t)(bm + m0 + i) * N + bn + n0]);
        dst[0] = make_float4(o[0], o[1], o[2], o[3]);
        dst[1] = make_float4(o[4], o[5], o[6], o[7]);
    }
}

// ---------------------------------------------------------------------------
// launch
// ---------------------------------------------------------------------------
extern "C" void kernel_launch(void* const* d_in, const int* in_sizes, int n_in,
                              void* d_out, int out_size)
{
    (void)in_sizes; (void)n_in; (void)out_size;
    const float* x  = (const float*)d_in[0];   // [32, 2048, 128]
    const float* A  = (const float*)d_in[1];   // [256, 256]
    const float* Bm = (const float*)d_in[2];   // [128, 256]
    const float* C  = (const float*)d_in[3];   // [256, 256]
    float* out = (float*)d_out;                // [32, 2048, 256]

    float* xB = nullptr;
    float* hs = nullptr;
    cudaGetSymbolAddress((void**)&xB, g_xB);   // pure query: capture-safe
    cudaGetSymbolAddress((void**)&hs, g_hs);

    const int M = B_SZ * T_LEN;                // 65536

    // 0) reset exchange tags (monotone within a launch; graph replays reuse)
    zero_xch_kernel<<<B_SZ, H_DIM>>>();
    // 1) xB = x @ Bm   (M x 128) @ (128 x 256)
    gemm_f32<<<dim3(M / 128, H_DIM / 128), 256>>>(x, Bm, xB, M, H_DIM, I_DIM);
    // 2) sequential tanh scan, 32 CTA-pairs exchanging through L2
    scan_kernel<<<B_SZ * 2, 256>>>(A);
    // 3) out = hs @ C  (M x 256) @ (256 x 256)
    gemm_f32<<<dim3(M / 128, H_DIM / 128), 256>>>(hs, C, out, M, H_DIM, H_DIM);
}